// round 1
// baseline (speedup 1.0000x reference)
#include <cuda_runtime.h>
#include <math_constants.h>

// Problem constants (fixed by reference)
constexpr int B = 8;
constexpr int N = 4096;
constexpr int M = 4096;

constexpr int THREADS = 256;   // threads per minpass block
constexpr int R       = 4;     // query points per thread (register tile)
constexpr int TN      = THREADS * R;   // 1024 query points per block
constexpr int SPLIT   = 8;             // M split into chunks for occupancy
constexpr int CHUNK   = M / SPLIT;     // 512 target points per block

// Scratch (no allocations allowed): partial mins per (batch, chunk, point)
__device__ float g_rowpart[B * SPLIT * N];
__device__ float g_colpart[B * SPLIT * M];
__device__ float g_acc[4];   // sum_rowmin, sum_sqrt_rowmin, sum_colmin, sum_unc

// ---------------- packed f32x2 helpers (Blackwell FFMA2 path) ----------------
__device__ __forceinline__ unsigned long long pack2(float x, float y) {
    unsigned long long r;
    asm("mov.b64 %0, {%1, %2};" : "=l"(r) : "f"(x), "f"(y));
    return r;
}
__device__ __forceinline__ unsigned long long fma2(unsigned long long a,
                                                   unsigned long long b,
                                                   unsigned long long c) {
    unsigned long long d;
    asm("fma.rn.f32x2 %0, %1, %2, %3;" : "=l"(d) : "l"(a), "l"(b), "l"(c));
    return d;
}
__device__ __forceinline__ void unpack2(unsigned long long v, float& lo, float& hi) {
    asm("mov.b64 {%0, %1}, %2;" : "=f"(lo), "=f"(hi) : "l"(v));
}

// ---------------------------------------------------------------------------
// minpass: for each point p in P (its TN-row slice), compute
//   min over a CHUNK of T of  d2(p,t) = ||p||^2 + ||t||^2 - 2 p.t
// Inner value tracked is (||t||^2 - 2 p.t); ||p||^2 added at the end
// (constant per row, commutes with min). Writes partial min per chunk.
// OUTSEL=0 -> g_rowpart, OUTSEL=1 -> g_colpart.
// ---------------------------------------------------------------------------
template <int OUTSEL>
__global__ void __launch_bounds__(THREADS)
minpass(const float* __restrict__ P, const float* __restrict__ T)
{
    __shared__ float4 s[CHUNK];   // [2k]   = (-2tx[2k], -2tx[2k+1], -2ty[2k], -2ty[2k+1])
                                  // [2k+1] = (-2tz[2k], -2tz[2k+1],  t2[2k],   t2[2k+1])
    const int tid   = threadIdx.x;
    const int split = blockIdx.x;
    const int ntile = blockIdx.y;
    const int b     = blockIdx.z;
    const int n0    = ntile * TN;
    const int mc0   = split * CHUNK;

    // Load + transform target chunk into smem (2 points per thread)
    {
        const int ma = 2 * tid;
        const float* ta = T + ((size_t)b * M + mc0 + ma) * 3;
        const float ax = ta[0], ay = ta[1], az = ta[2];
        const float bx = ta[3], by = ta[4], bz = ta[5];
        const float a2 = ax * ax + ay * ay + az * az;
        const float b2 = bx * bx + by * by + bz * bz;
        s[ma]     = make_float4(-2.f * ax, -2.f * bx, -2.f * ay, -2.f * by);
        s[ma + 1] = make_float4(-2.f * az, -2.f * bz, a2, b2);
    }

    // Load R query points into registers, broadcast-packed for f32x2
    unsigned long long px2[R], py2[R], pz2[R];
    float pn2[R], rlo[R], rhi[R];
#pragma unroll
    for (int j = 0; j < R; j++) {
        const int nn = n0 + tid + THREADS * j;
        const float* p = P + ((size_t)b * N + nn) * 3;
        const float x = p[0], y = p[1], z = p[2];
        pn2[j] = x * x + y * y + z * z;
        px2[j] = pack2(x, x);
        py2[j] = pack2(y, y);
        pz2[j] = pack2(z, z);
        rlo[j] = CUDART_INF_F;
        rhi[j] = CUDART_INF_F;
    }
    __syncthreads();

    const ulonglong2* s64 = reinterpret_cast<const ulonglong2*>(s);
#pragma unroll 4
    for (int k = 0; k < CHUNK / 2; k++) {
        const ulonglong2 v0 = s64[2 * k];       // {tx2 pair, ty2 pair}
        const ulonglong2 v1 = s64[2 * k + 1];   // {tz2 pair, t2 pair}
#pragma unroll
        for (int j = 0; j < R; j++) {
            unsigned long long acc = fma2(pz2[j], v1.x, v1.y);  // -2 z tz + t2
            acc = fma2(py2[j], v0.y, acc);
            acc = fma2(px2[j], v0.x, acc);                      // t2 - 2 p.t (x2)
            float lo, hi;
            unpack2(acc, lo, hi);
            rlo[j] = fminf(rlo[j], lo);
            rhi[j] = fminf(rhi[j], hi);
        }
    }

    float* outp = OUTSEL ? g_colpart : g_rowpart;
    float* o = outp + (size_t)(b * SPLIT + split) * N;
#pragma unroll
    for (int j = 0; j < R; j++) {
        const int nn = n0 + tid + THREADS * j;
        o[nn] = pn2[j] + fminf(rlo[j], rhi[j]);   // true squared distance min (partial)
    }
}

// ---------------------------------------------------------------------------
__global__ void zero_acc_kernel()
{
    if (threadIdx.x < 4) g_acc[threadIdx.x] = 0.f;
}

__global__ void reduce_kernel(const float* __restrict__ unc)
{
    float s_row = 0.f, s_sqrt = 0.f, s_col = 0.f, s_unc = 0.f;
    const int stride = gridDim.x * blockDim.x;
    for (int idx = blockIdx.x * blockDim.x + threadIdx.x; idx < B * N; idx += stride) {
        const int b = idx >> 12;          // N == 4096
        const int n = idx & (N - 1);

        const float* p = g_rowpart + (size_t)b * SPLIT * N + n;
        float m = p[0];
#pragma unroll
        for (int s2 = 1; s2 < SPLIT; s2++) m = fminf(m, p[(size_t)s2 * N]);
        s_row  += m;
        s_sqrt += sqrtf(fmaxf(m, 0.f));

        const float* q = g_colpart + (size_t)b * SPLIT * M + n;
        float mc = q[0];
#pragma unroll
        for (int s2 = 1; s2 < SPLIT; s2++) mc = fminf(mc, q[(size_t)s2 * M]);
        s_col += mc;

        s_unc += unc[idx];
    }
    // warp reduce, then one atomicAdd per warp
#pragma unroll
    for (int o = 16; o > 0; o >>= 1) {
        s_row  += __shfl_down_sync(0xffffffffu, s_row,  o);
        s_sqrt += __shfl_down_sync(0xffffffffu, s_sqrt, o);
        s_col  += __shfl_down_sync(0xffffffffu, s_col,  o);
        s_unc  += __shfl_down_sync(0xffffffffu, s_unc,  o);
    }
    if ((threadIdx.x & 31) == 0) {
        atomicAdd(&g_acc[0], s_row);
        atomicAdd(&g_acc[1], s_sqrt);
        atomicAdd(&g_acc[2], s_col);
        atomicAdd(&g_acc[3], s_unc);
    }
}

__global__ void finalize_kernel(float* __restrict__ out)
{
    const float inv = 1.0f / (float)(B * N);   // B*N == B*M
    const float chamfer = (g_acc[0] + g_acc[2]) * inv;  // mean rowmin + mean colmin
    const float emd     = g_acc[1] * inv;                // mean sqrt(rowmin)
    const float unc     = g_acc[3] * inv;                // mean uncertainty
    out[0] = chamfer * 1.0f + emd * 0.5f + unc * 0.01f;
}

// ---------------------------------------------------------------------------
extern "C" void kernel_launch(void* const* d_in, const int* in_sizes, int n_in,
                              void* d_out, int out_size)
{
    const float* pred = (const float*)d_in[0];   // [B, N, 3]
    const float* targ = (const float*)d_in[1];   // [B, M, 3]
    const float* unc  = (const float*)d_in[2];   // [B, N]
    float* out = (float*)d_out;

    zero_acc_kernel<<<1, 32>>>();

    dim3 grid(SPLIT, N / TN, B);                 // (8, 4, 8) = 256 blocks
    minpass<0><<<grid, THREADS>>>(pred, targ);   // rowmin: per pred point, min over targets
    minpass<1><<<grid, THREADS>>>(targ, pred);   // colmin: per target point, min over preds

    reduce_kernel<<<64, 256>>>(unc);
    finalize_kernel<<<1, 1>>>(out);
}

// round 3
// speedup vs baseline: 1.1110x; 1.1110x over previous
#include <cuda_runtime.h>
#include <math_constants.h>

// Problem constants (fixed by reference)
constexpr int B = 8;
constexpr int N = 4096;
constexpr int M = 4096;

constexpr int THREADS = 256;          // threads per minpass block
constexpr int R       = 4;            // query points per thread (register tile)
constexpr int TN      = THREADS * R;  // 1024 query points per block
constexpr int NTILES  = N / TN;       // 4
constexpr int SPLIT   = 16;           // M split into chunks (occupancy / balance)
constexpr int CHUNK   = M / SPLIT;    // 256 target points per block

// Scratch (no allocations allowed): partial mins per (pass, batch, chunk, point)
__device__ float g_rowpart[B * SPLIT * N];
__device__ float g_colpart[B * SPLIT * M];
__device__ float g_acc[4];   // sum_rowmin, sum_sqrt_rowmin, sum_colmin, sum_unc

// ---------------- packed f32x2 helpers (Blackwell FFMA2 path) ----------------
__device__ __forceinline__ unsigned long long pack2(float x, float y) {
    unsigned long long r;
    asm("mov.b64 %0, {%1, %2};" : "=l"(r) : "f"(x), "f"(y));
    return r;
}
__device__ __forceinline__ unsigned long long fma2(unsigned long long a,
                                                   unsigned long long b,
                                                   unsigned long long c) {
    unsigned long long d;
    asm("fma.rn.f32x2 %0, %1, %2, %3;" : "=l"(d) : "l"(a), "l"(b), "l"(c));
    return d;
}
__device__ __forceinline__ void unpack2(unsigned long long v, float& lo, float& hi) {
    asm("mov.b64 {%0, %1}, %2;" : "=f"(lo), "=f"(hi) : "l"(v));
}

// ---------------------------------------------------------------------------
// Fused bidirectional minpass.
//   pass 0: P = pred, T = targ  -> g_rowpart   (min over targets per pred pt)
//   pass 1: P = targ, T = pred  -> g_colpart   (min over preds per target pt)
// Tracks (||t||^2 - 2 p.t) in the inner loop; adds ||p||^2 at the end
// (constant per row, commutes with min).
// ---------------------------------------------------------------------------
__global__ void __launch_bounds__(THREADS)
minpass_fused(const float* __restrict__ pred, const float* __restrict__ targ)
{
    __shared__ float4 s[CHUNK];   // [2k]   = (-2tx[2k], -2tx[2k+1], -2ty[2k], -2ty[2k+1])
                                  // [2k+1] = (-2tz[2k], -2tz[2k+1],  t2[2k],   t2[2k+1])
    const int tid   = threadIdx.x;
    const int split = blockIdx.x;
    const int ntile = blockIdx.y;
    const int zz    = blockIdx.z;        // [0, 2*B)
    const int b     = zz & (B - 1);
    const int pass  = zz >> 3;
    const int n0    = ntile * TN;
    const int mc0   = split * CHUNK;

    const float* P = pass ? targ : pred;
    const float* T = pass ? pred : targ;
    float* outp    = pass ? g_colpart : g_rowpart;

    // Load + transform target chunk into smem (2 points per thread, tid<CHUNK/2)
    if (tid < CHUNK / 2) {
        const int ma = 2 * tid;
        const float* ta = T + ((size_t)b * M + mc0 + ma) * 3;
        const float ax = ta[0], ay = ta[1], az = ta[2];
        const float bx = ta[3], by = ta[4], bz = ta[5];
        const float a2 = ax * ax + ay * ay + az * az;
        const float b2 = bx * bx + by * by + bz * bz;
        s[ma]     = make_float4(-2.f * ax, -2.f * bx, -2.f * ay, -2.f * by);
        s[ma + 1] = make_float4(-2.f * az, -2.f * bz, a2, b2);
    }

    // Load R query points into registers, broadcast-packed for f32x2
    unsigned long long px2[R], py2[R], pz2[R];
    float pn2[R], rlo[R], rhi[R];
#pragma unroll
    for (int j = 0; j < R; j++) {
        const int nn = n0 + tid + THREADS * j;
        const float* p = P + ((size_t)b * N + nn) * 3;
        const float x = p[0], y = p[1], z = p[2];
        pn2[j] = x * x + y * y + z * z;
        px2[j] = pack2(x, x);
        py2[j] = pack2(y, y);
        pz2[j] = pack2(z, z);
        rlo[j] = CUDART_INF_F;
        rhi[j] = CUDART_INF_F;
    }
    __syncthreads();

    const ulonglong2* s64 = reinterpret_cast<const ulonglong2*>(s);
#pragma unroll 4
    for (int k = 0; k < CHUNK / 2; k++) {
        const ulonglong2 v0 = s64[2 * k];       // {tx2 pair, ty2 pair}
        const ulonglong2 v1 = s64[2 * k + 1];   // {tz2 pair, t2 pair}
#pragma unroll
        for (int j = 0; j < R; j++) {
            unsigned long long acc = fma2(pz2[j], v1.x, v1.y);  // -2 z tz + t2
            acc = fma2(py2[j], v0.y, acc);
            acc = fma2(px2[j], v0.x, acc);                      // t2 - 2 p.t (x2)
            float lo, hi;
            unpack2(acc, lo, hi);
            rlo[j] = fminf(rlo[j], lo);
            rhi[j] = fminf(rhi[j], hi);
        }
    }

    float* o = outp + (size_t)(b * SPLIT + split) * N;
#pragma unroll
    for (int j = 0; j < R; j++) {
        const int nn = n0 + tid + THREADS * j;
        o[nn] = pn2[j] + fminf(rlo[j], rhi[j]);   // partial min of true squared dist
    }
}

// ---------------------------------------------------------------------------
__global__ void zero_acc_kernel()
{
    if (threadIdx.x < 4) g_acc[threadIdx.x] = 0.f;
}

// One idx per thread; 33 independent L2-resident loads each -> latency hidden
// by thread count (32768 threads) + MLP.
__global__ void __launch_bounds__(256) reduce_kernel(const float* __restrict__ unc)
{
    const int idx = blockIdx.x * blockDim.x + threadIdx.x;   // [0, B*N)
    const int b = idx >> 12;          // N == 4096
    const int n = idx & (N - 1);

    const float* p = g_rowpart + (size_t)b * SPLIT * N + n;
    float m = p[0];
#pragma unroll
    for (int s2 = 1; s2 < SPLIT; s2++) m = fminf(m, __ldg(p + (size_t)s2 * N));
    float s_row  = m;
    float s_sqrt = sqrtf(fmaxf(m, 0.f));

    const float* q = g_colpart + (size_t)b * SPLIT * M + n;
    float mc = q[0];
#pragma unroll
    for (int s2 = 1; s2 < SPLIT; s2++) mc = fminf(mc, __ldg(q + (size_t)s2 * M));
    float s_col = mc;

    float s_unc = unc[idx];

    // warp reduce, then one atomicAdd per warp
#pragma unroll
    for (int o = 16; o > 0; o >>= 1) {
        s_row  += __shfl_down_sync(0xffffffffu, s_row,  o);
        s_sqrt += __shfl_down_sync(0xffffffffu, s_sqrt, o);
        s_col  += __shfl_down_sync(0xffffffffu, s_col,  o);
        s_unc  += __shfl_down_sync(0xffffffffu, s_unc,  o);
    }
    if ((threadIdx.x & 31) == 0) {
        atomicAdd(&g_acc[0], s_row);
        atomicAdd(&g_acc[1], s_sqrt);
        atomicAdd(&g_acc[2], s_col);
        atomicAdd(&g_acc[3], s_unc);
    }
}

__global__ void finalize_kernel(float* __restrict__ out)
{
    const float inv = 1.0f / (float)(B * N);   // B*N == B*M
    const float chamfer = (g_acc[0] + g_acc[2]) * inv;  // mean rowmin + mean colmin
    const float emd     = g_acc[1] * inv;                // mean sqrt(rowmin)
    const float unc     = g_acc[3] * inv;                // mean uncertainty
    out[0] = chamfer * 1.0f + emd * 0.5f + unc * 0.01f;
}

// ---------------------------------------------------------------------------
extern "C" void kernel_launch(void* const* d_in, const int* in_sizes, int n_in,
                              void* d_out, int out_size)
{
    const float* pred = (const float*)d_in[0];   // [B, N, 3]
    const float* targ = (const float*)d_in[1];   // [B, M, 3]
    const float* unc  = (const float*)d_in[2];   // [B, N]
    float* out = (float*)d_out;

    zero_acc_kernel<<<1, 32>>>();

    dim3 grid(SPLIT, NTILES, 2 * B);             // 16 x 4 x 16 = 1024 blocks
    minpass_fused<<<grid, THREADS>>>(pred, targ);

    reduce_kernel<<<(B * N) / 256, 256>>>(unc);  // 128 blocks x 256
    finalize_kernel<<<1, 1>>>(out);
}